// round 15
// baseline (speedup 1.0000x reference)
#include <cuda_runtime.h>
#include <math.h>
#include <stdint.h>

// ---------------- problem constants ----------------
#define NE    7
#define NV    3
#define FDIM  128
#define HID   128
#define VED   16
#define PED   39
#define GIND  19
#define OUTD  3

// ---------------- tiling ----------------
#define MT    32     // points per block (2 blocks/SM)
#define NTHR  128    // 4 warps; microtile 4(m) x 8(n), thread grid 16 x 8

// ---------------- shared memory layout (floats) ----------------
#define SSTR     132
#define SA_OFF   0
#define SB_OFF   (MT*SSTR)
#define HACC_OFF (SB_OFF + MT*SSTR)
#define W_OFF    (HACC_OFF + 3*MT*128)
#define PE_OFF   (W_OFF + 32*128)
#define GIN_OFF  (PE_OFF + MT*40)
#define GW_OFF   (GIN_OFF + MT*20)
#define LOG_OFF  (GW_OFF + 3*MT*8)
#define PROJ_OFF (LOG_OFF + MT*8)
#define SMEMF    (PROJ_OFF + 3*128)          // 110.0 KB

// =================================================================
// FROZEN NUMERICS (passing recipe, rel_err 2.43e-4):
// layer sine = float-float glibc-poly; PE sine + gate exp = FP64;
// IEEE div; sequential-k fused-FMA GEMMs; unfused combine.
// This round changes ONLY the thread mapping (4x8 microtile).
// =================================================================

// ---------- FP64 reference path (PE + gate exp only) ----------
struct gsincos_t {
    double sign[4];
    double c0, c1, c2, c3, c4;
    double s1, s2, s3;
};

__constant__ gsincos_t G_SINCOS[2] = {
  {
    { 1.0, -1.0, -1.0, 1.0 },
     0x1p+0,
    -0x1.ffffffd0c621cp-2,
     0x1.55553e1068f19p-5,
    -0x1.6c087e89a359dp-10,
     0x1.99343027bf8c3p-16,
    -0x1.555545995a603p-3,
     0x1.1107605230bc4p-7,
    -0x1.994eb3774cf24p-13
  },
  {
    { 1.0, -1.0, -1.0, 1.0 },
    -0x1p+0,
     0x1.ffffffd0c621cp-2,
    -0x1.55553e1068f19p-5,
     0x1.6c087e89a359dp-10,
    -0x1.99343027bf8c3p-16,
    -0x1.555545995a603p-3,
     0x1.1107605230bc4p-7,
    -0x1.994eb3774cf24p-13
  }
};

__device__ __forceinline__ uint32_t abstop12f(float x) {
    return (__float_as_uint(x) >> 20) & 0x7ffu;
}

__device__ __forceinline__ float g_sinf_poly(double x, double x2,
                                             const gsincos_t* p, int n) {
    if ((n & 1) == 0) {
        double x3 = x2 * x;
        double s1 = fma(x2, p->s3, p->s2);
        double x5 = x3 * x2;
        double s  = fma(x3, p->s1, x);
        return (float)fma(x5, s1, s);
    } else {
        double x4 = x2 * x2;
        double c2 = fma(x2, p->c4, p->c3);
        double c1 = fma(x2, p->c1, p->c0);
        double x6 = x4 * x2;
        double c  = fma(x4, p->c2, c1);
        return (float)fma(x6, c2, c);
    }
}

__device__ __forceinline__ double cw_reduce(double x, int* np) {
    double fn = rint(x * 0x1.45F306DC9C883p-1);
    double r  = fma(fn, -0x1.921FB54442D18p+0, x);
    r = fma(fn, -0x1.1A62633145C07p-54, r);
    *np = (int)fn;
    return r;
}

__device__ __forceinline__ float g_sinf(float y) {
    double x = (double)y;
    const gsincos_t* p = &G_SINCOS[0];
    uint32_t at = abstop12f(y);
    if (at < 0x3F4u) {
        if (at < 0x398u) return y;
        return g_sinf_poly(x, x * x, p, 0);
    }
    int n;
    x = cw_reduce(x, &n);
    double s = p->sign[n & 3];
    if (n & 2) p = &G_SINCOS[1];
    return g_sinf_poly(x * s, x * x, p, n);
}

__device__ __forceinline__ float g_cosf(float y) {
    double x = (double)y;
    const gsincos_t* p = &G_SINCOS[0];
    uint32_t at = abstop12f(y);
    if (at < 0x3F4u) {
        if (at < 0x398u) return 1.0f;
        return g_sinf_poly(x, x * x, p, 1);
    }
    int n;
    x = cw_reduce(x, &n);
    double s = p->sign[(n + 1) & 3];
    if ((n + 1) & 2) p = &G_SINCOS[1];
    return g_sinf_poly(x * s, x * x, p, n ^ 1);
}

__device__ __forceinline__ float g_expf(float xf) {
    double x = (double)xf;
    double fn = rint(x * 1.44269504088896338700e+00);
    double r  = fma(fn, -6.93147180369123816490e-01, x);
    r = fma(fn, -1.90821492927058770002e-10, r);
    double p =               1.0/479001600.0;
    p = fma(p, r, 1.0/39916800.0);
    p = fma(p, r, 1.0/3628800.0);
    p = fma(p, r, 1.0/362880.0);
    p = fma(p, r, 1.0/40320.0);
    p = fma(p, r, 1.0/5040.0);
    p = fma(p, r, 1.0/720.0);
    p = fma(p, r, 1.0/120.0);
    p = fma(p, r, 1.0/24.0);
    p = fma(p, r, 1.0/6.0);
    p = fma(p, r, 0.5);
    p = fma(p, r, 1.0);
    p = fma(p, r, 1.0);
    int n = (int)fn;
    double sc = __longlong_as_double((long long)(1023 + n) << 52);
    return (float)(p * sc);
}

// ---------- float-float (df) machinery ----------
struct df { float h, l; };

__device__ __forceinline__ df df_two_prod(float a, float b) {
    float p = a * b; float e = fmaf(a, b, -p); return {p, e};
}
__device__ __forceinline__ df df_fast2sum(float a, float b) {
    float s = a + b; float e = b - (s - a); return {s, e};
}
__device__ __forceinline__ df df_two_sum(float a, float b) {
    float s = a + b; float bb = s - a;
    float e = (a - (s - bb)) + (b - bb); return {s, e};
}
__device__ __forceinline__ df df_mul(df a, df b) {
    float p = a.h * b.h;
    float e = fmaf(a.h, b.h, -p);
    e = fmaf(a.h, b.l, e);
    e = fmaf(a.l, b.h, e);
    return df_fast2sum(p, e);
}
__device__ __forceinline__ df df_sqr(df a) {
    float p = a.h * a.h;
    float e = fmaf(a.h, a.h, -p);
    e = fmaf(a.h + a.h, a.l, e);
    return df_fast2sum(p, e);
}
__device__ __forceinline__ df df_add(df a, df b) {
    df s = df_two_sum(a.h, b.h);
    float e = (s.l + a.l) + b.l;
    return df_fast2sum(s.h, e);
}

#define DFC(name, dval) \
    constexpr float name##_H = (float)(dval); \
    constexpr float name##_L = (float)((dval) - (double)((float)(dval)));

DFC(INV2PI, 0x1.45F306DC9C883p-1)
constexpr double D_PI2  = 0x1.921FB54442D18p+0;
constexpr double D_PI2L = 0x1.1A62633145C07p-54;
constexpr float P2H = (float)D_PI2;
constexpr float P2M = (float)(D_PI2 - (double)P2H + D_PI2L);
constexpr float P2L = (float)(D_PI2 - (double)P2H - (double)P2M + D_PI2L);

DFC(KS1, -0x1.555545995a603p-3)
DFC(KS2,  0x1.1107605230bc4p-7)
DFC(KS3, -0x1.994eb3774cf24p-13)
DFC(KC1, -0x1.ffffffd0c621cp-2)
DFC(KC2,  0x1.55553e1068f19p-5)
DFC(KC3, -0x1.6c087e89a359dp-10)
DFC(KC4,  0x1.99343027bf8c3p-16)

__device__ __forceinline__ float ff_poly(df x, df x2, int n, bool cneg) {
    if ((n & 1) == 0) {
        df x3 = df_mul(x2, x);
        df s1 = df_add(df_mul(x2, {KS3_H, KS3_L}), {KS2_H, KS2_L});
        df x5 = df_mul(x3, x2);
        df s  = df_add(df_mul(x3, {KS1_H, KS1_L}), x);
        df r  = df_add(df_mul(x5, s1), s);
        return r.h + r.l;
    } else {
        df x4 = df_sqr(x2);
        df c2 = df_add(df_mul(x2, {KC4_H, KC4_L}), {KC3_H, KC3_L});
        df c1 = df_add(df_mul(x2, {KC1_H, KC1_L}), {1.0f, 0.0f});
        df x6 = df_mul(x4, x2);
        df c  = df_add(df_mul(x4, {KC2_H, KC2_L}), c1);
        df r  = df_add(df_mul(x6, c2), c);
        float v = r.h + r.l;
        return cneg ? -v : v;
    }
}

__device__ __forceinline__ float ff_sinf(float y) {
    uint32_t at = abstop12f(y);
    if (at < 0x3F4u) {
        if (at < 0x398u) return y;
        df x = {y, 0.0f};
        return ff_poly(x, df_sqr(x), 0, false);
    }
    df z = df_two_prod(y, INV2PI_H);
    float zl = fmaf(y, INV2PI_L, z.l);
    float fn0 = rintf(z.h);
    float d = (z.h - fn0) + zl;
    float fn = fn0 + rintf(d);
    int n = (int)fn;
    float ah = fn * P2H; float ae = fmaf(fn, P2H, -ah);
    float bh = fn * P2M; float be = fmaf(fn, P2M, -bh);
    df s1 = df_two_sum(y,   -ah);
    df s2 = df_two_sum(s1.h, -ae);
    df s3 = df_two_sum(s2.h, -bh);
    float lo = (s1.l + s2.l) + s3.l;
    lo -= be;
    lo = fmaf(fn, -P2L, lo);
    df r = df_fast2sum(s3.h, lo);
    float sg = (((n >> 1) ^ n) & 1) ? -1.0f : 1.0f;
    df xs = { r.h * sg, r.l * sg };
    return ff_poly(xs, df_sqr(xs), n, (n & 2) != 0);
}

__device__ __forceinline__ float siren_sin(float v) {
    return ff_sinf(30.0f * v);
}

// ---------------------------------------------------------------
// One dense layer for the 32-point tile (128 threads):
// microtile 4(m) x 8(n); grid 16(tx=n) x 8(ty=m).
// Sequential-k fused-FMA per output element (frozen order).
// W fragment reused across 4 rows -> smem traffic halved.
// ---------------------------------------------------------------
template<bool DOSIN>
__device__ __forceinline__ void layer_gemm(float* sm, int inOff, int inStride, int K,
        const float* __restrict__ gW, const float* __restrict__ gB,
        int outOff, int outStride)
{
    const int tid = threadIdx.x;
    const int tx = tid & 15, ty = tid >> 4;    // 16 x 8
    const int n0 = tx * 8, m0 = ty * 4;

    float acc[4][8];
#pragma unroll
    for (int i = 0; i < 4; i++)
#pragma unroll
        for (int j = 0; j < 8; j++) acc[i][j] = 0.0f;

    float* sW = sm + W_OFF;
    const float* sA = sm + inOff;

    for (int kc = 0; kc < K; kc += 32) {
        const int kcur = min(32, K - kc);
        __syncthreads();
        {
            const float4* src = (const float4*)(gW + (size_t)kc * 128);
            float4* dst = (float4*)sW;
            const int tot4 = kcur * 32;
            for (int i = tid; i < tot4; i += NTHR) dst[i] = src[i];
        }
        __syncthreads();
#pragma unroll 4
        for (int k = 0; k < kcur; k++) {
            const float a0 = sA[(m0 + 0) * inStride + kc + k];
            const float a1 = sA[(m0 + 1) * inStride + kc + k];
            const float a2 = sA[(m0 + 2) * inStride + kc + k];
            const float a3 = sA[(m0 + 3) * inStride + kc + k];
            const float* wr = sW + k * 128 + n0;
#pragma unroll
            for (int j = 0; j < 8; j++) {
                const float w = wr[j];
                acc[0][j] = fmaf(a0, w, acc[0][j]);
                acc[1][j] = fmaf(a1, w, acc[1][j]);
                acc[2][j] = fmaf(a2, w, acc[2][j]);
                acc[3][j] = fmaf(a3, w, acc[3][j]);
            }
        }
    }

    float* sO = sm + outOff;
#pragma unroll
    for (int i = 0; i < 4; i++) {
#pragma unroll
        for (int j = 0; j < 8; j++) {
            float v = acc[i][j] + gB[n0 + j];
            if (DOSIN) v = siren_sin(v);
            sO[(m0 + i) * outStride + n0 + j] = v;
        }
    }
    __syncthreads();
}

// ---------------------------------------------------------------
__global__ void __launch_bounds__(NTHR, 2)
moe_fused_kernel(const float* __restrict__ coords,
                 const float* __restrict__ view_emb,
                 const float* __restrict__ proj_W,
                 const float* __restrict__ gate_W0, const float* __restrict__ gate_b0,
                 const float* __restrict__ gate_Wh, const float* __restrict__ gate_bh,
                 const float* __restrict__ gate_Wo, const float* __restrict__ gate_bo,
                 const float* __restrict__ exp_W0, const float* __restrict__ exp_b0,
                 const float* __restrict__ exp_Wh, const float* __restrict__ exp_bh,
                 const float* __restrict__ exp_Wo, const float* __restrict__ exp_bo,
                 const float* __restrict__ dec_W0, const float* __restrict__ dec_b0,
                 const float* __restrict__ dec_Wh, const float* __restrict__ dec_bh,
                 const float* __restrict__ dec_Wo, const float* __restrict__ dec_bo,
                 float* __restrict__ out, int npts)
{
    extern __shared__ float sm[];
    const int tid = threadIdx.x;
    const int gm0 = blockIdx.x * MT;

    // ---------- positional encoding: FP64 path (chain head) ----------
    for (int idx = tid; idx < MT * PED; idx += NTHR) {
        int m = idx / PED, c = idx % PED;
        float v;
        if (c < 3) {
            v = coords[(size_t)(gm0 + m) * 3 + c];
        } else {
            int r = c - 3;
            int i = r / 12;
            int rr = r % 12;
            int f = rr % 6;
            float x = coords[(size_t)(gm0 + m) * 3 + i];
            float freq = 3.14159265358979323846f * (float)(1 << f);
            float a = x * freq;
            v = (rr < 6) ? g_sinf(a) : g_cosf(a);
        }
        sm[PE_OFF + m * 40 + c] = v;
    }

    // ---------- projvec[v][n] = vemb[v] @ proj_W ----------
    for (int idx = tid; idx < NV * 128; idx += NTHR) {
        int v = idx >> 7, n = idx & 127;
        float a = 0.0f;
#pragma unroll
        for (int k = 0; k < VED; k++)
            a = fmaf(view_emb[v * VED + k], proj_W[k * 128 + n], a);
        sm[PROJ_OFF + idx] = a;
    }

    for (int idx = tid; idx < NV * MT * 128; idx += NTHR)
        sm[HACC_OFF + idx] = 0.0f;
    __syncthreads();

    // ---------- gate MLP per view -> top-2 normalized weights ----------
    for (int v = 0; v < NV; v++) {
        __syncthreads();
        for (int idx = tid; idx < MT * 20; idx += NTHR) {
            int m = idx / 20, c = idx % 20;
            float x;
            if (c < 3)       x = coords[(size_t)(gm0 + m) * 3 + c];
            else if (c < 19) x = view_emb[v * VED + (c - 3)];
            else             x = 0.0f;
            sm[GIN_OFF + idx] = x;
        }
        layer_gemm<true>(sm, GIN_OFF, 20, GIND, gate_W0, gate_b0, SA_OFF, SSTR);
        layer_gemm<true>(sm, SA_OFF, SSTR, HID, gate_Wh,             gate_bh,       SB_OFF, SSTR);
        layer_gemm<true>(sm, SB_OFF, SSTR, HID, gate_Wh + HID * HID, gate_bh + HID, SA_OFF, SSTR);

        for (int idx = tid; idx < MT * NE; idx += NTHR) {
            int m = idx / NE, e = idx % NE;
            float a = 0.0f;
            const float* h = sm + SA_OFF + m * SSTR;
            for (int k = 0; k < HID; k++)
                a = fmaf(h[k], gate_Wo[k * NE + e], a);
            sm[LOG_OFF + m * 8 + e] = a + gate_bo[e];
        }
        __syncthreads();

        // softmax + top-2 + renormalize: FP64 exp, IEEE div, ref tie order
        if (tid < MT) {
            float l[NE];
            float mx = -1e30f;
            for (int e = 0; e < NE; e++) { l[e] = sm[LOG_OFF + tid * 8 + e]; mx = fmaxf(mx, l[e]); }
            float p[NE]; float s = 0.0f;
            for (int e = 0; e < NE; e++) { p[e] = g_expf(l[e] - mx); s += p[e]; }
            float p1 = -1.0f, p2 = -1.0f; int i1 = -1, i2 = -1;
            for (int e = 0; e < NE; e++) {
                float pe_ = __fdiv_rn(p[e], s);
                p[e] = pe_;
                if (pe_ > p1)      { p2 = p1; i2 = i1; p1 = pe_; i1 = e; }
                else if (pe_ > p2) { p2 = pe_; i2 = e; }
            }
            float den = (p1 + p2) + 1e-9f;
            for (int e = 0; e < NE; e++) {
                float w = 0.0f;
                if (e == i1)      w = __fdiv_rn(p1, den);
                else if (e == i2) w = __fdiv_rn(p2, den);
                sm[GW_OFF + (v * MT + tid) * 8 + e] = w;
            }
        }
        __syncthreads();
    }

    // ---------- experts ----------
    for (int e = 0; e < NE; e++) {
        const float* W0 = exp_W0 + (size_t)e * PED * HID;
        const float* Wh = exp_Wh + (size_t)e * 2 * HID * HID;
        const float* Wo = exp_Wo + (size_t)e * HID * FDIM;
        layer_gemm<true >(sm, PE_OFF, 40, PED, W0,             exp_b0 + e * HID,           SA_OFF, SSTR);
        layer_gemm<true >(sm, SA_OFF, SSTR, HID, Wh,             exp_bh + e * 2 * HID,       SB_OFF, SSTR);
        layer_gemm<true >(sm, SB_OFF, SSTR, HID, Wh + HID * HID, exp_bh + e * 2 * HID + HID, SA_OFF, SSTR);
        layer_gemm<false>(sm, SA_OFF, SSTR, HID, Wo,             exp_bo + e * FDIM,          SB_OFF, SSTR);

        const int tx = tid & 15, ty = tid >> 4;
        const int n0 = tx * 8, m0 = ty * 4;
#pragma unroll
        for (int v = 0; v < NV; v++) {
#pragma unroll
            for (int i = 0; i < 4; i++) {
                const float wv = sm[GW_OFF + (v * MT + m0 + i) * 8 + e];
                float* hb = sm + HACC_OFF + ((v * MT + m0 + i) << 7) + n0;
                const float* fb = sm + SB_OFF + (m0 + i) * SSTR + n0;
#pragma unroll
                for (int j = 0; j < 8; j++) {
                    float t = __fmul_rn(wv, fb[j]);
                    hb[j] = __fadd_rn(hb[j], t);
                }
            }
        }
        __syncthreads();
    }

    // add proj AFTER the expert sum
    for (int idx = tid; idx < NV * MT * 128; idx += NTHR) {
        int v = idx / (MT * 128);
        int n = idx & 127;
        sm[HACC_OFF + idx] = __fadd_rn(sm[HACC_OFF + idx], sm[PROJ_OFF + v * 128 + n]);
    }
    __syncthreads();

    // ---------- per-view decoder ----------
    for (int v = 0; v < NV; v++) {
        const float* W0 = dec_W0 + (size_t)v * FDIM * HID;
        const float* Wh = dec_Wh + (size_t)v * 2 * HID * HID;
        layer_gemm<true>(sm, HACC_OFF + v * MT * 128, 128, FDIM, W0, dec_b0 + v * HID, SA_OFF, SSTR);
        layer_gemm<true>(sm, SA_OFF, SSTR, HID, Wh,             dec_bh + v * 2 * HID,       SB_OFF, SSTR);
        layer_gemm<true>(sm, SB_OFF, SSTR, HID, Wh + HID * HID, dec_bh + v * 2 * HID + HID, SA_OFF, SSTR);

        for (int idx = tid; idx < MT * OUTD; idx += NTHR) {
            int m = idx / OUTD, o = idx % OUTD;
            float a = 0.0f;
            const float* h = sm + SA_OFF + m * SSTR;
            const float* w = dec_Wo + (size_t)v * HID * OUTD;
            for (int k = 0; k < HID; k++)
                a = fmaf(h[k], w[k * OUTD + o], a);
            out[((size_t)v * npts + gm0 + m) * OUTD + o] = a + dec_bo[v * OUTD + o];
        }
        __syncthreads();
    }
}

extern "C" void kernel_launch(void* const* d_in, const int* in_sizes, int n_in,
                              void* d_out, int out_size) {
    const float* coords   = (const float*)d_in[0];
    const float* view_emb = (const float*)d_in[1];
    const float* proj_W   = (const float*)d_in[2];
    const float* gate_W0  = (const float*)d_in[3];
    const float* gate_b0  = (const float*)d_in[4];
    const float* gate_Wh  = (const float*)d_in[5];
    const float* gate_bh  = (const float*)d_in[6];
    const float* gate_Wo  = (const float*)d_in[7];
    const float* gate_bo  = (const float*)d_in[8];
    const float* exp_W0   = (const float*)d_in[9];
    const float* exp_b0   = (const float*)d_in[10];
    const float* exp_Wh   = (const float*)d_in[11];
    const float* exp_bh   = (const float*)d_in[12];
    const float* exp_Wo   = (const float*)d_in[13];
    const float* exp_bo   = (const float*)d_in[14];
    const float* dec_W0   = (const float*)d_in[15];
    const float* dec_b0   = (const float*)d_in[16];
    const float* dec_Wh   = (const float*)d_in[17];
    const float* dec_bh   = (const float*)d_in[18];
    const float* dec_Wo   = (const float*)d_in[19];
    const float* dec_bo   = (const float*)d_in[20];

    const int npts = in_sizes[0] / 3;      // 65536
    const int grid = npts / MT;            // 2048
    const size_t shmem = (size_t)SMEMF * sizeof(float);   // 110.0 KB

    cudaFuncSetAttribute(moe_fused_kernel,
                         cudaFuncAttributeMaxDynamicSharedMemorySize, (int)shmem);

    moe_fused_kernel<<<grid, NTHR, shmem>>>(
        coords, view_emb, proj_W,
        gate_W0, gate_b0, gate_Wh, gate_bh, gate_Wo, gate_bo,
        exp_W0, exp_b0, exp_Wh, exp_bh, exp_Wo, exp_bo,
        dec_W0, dec_b0, dec_Wh, dec_bh, dec_Wo, dec_bo,
        (float*)d_out, npts);
}

// round 16
// speedup vs baseline: 1.2803x; 1.2803x over previous
#include <cuda_runtime.h>
#include <math.h>
#include <stdint.h>

// ---------------- problem constants ----------------
#define NE    7
#define NV    3
#define FDIM  128
#define HID   128
#define VED   16
#define PED   39
#define GIND  19
#define OUTD  3

// ---------------- tiling (R14 shape: best known) ----------------
#define MT    32     // points per block (2 blocks/SM)
#define NTHR  256    // 8 warps; microtile 2(m) x 8(n), grid 16 x 16

// ---------------- shared memory layout (floats) ----------------
#define SSTR     132
#define SA_OFF   0
#define SB_OFF   (MT*SSTR)
#define HACC_OFF (SB_OFF + MT*SSTR)
#define W_OFF    (HACC_OFF + 3*MT*128)
#define PE_OFF   (W_OFF + 32*128)
#define GIN_OFF  (PE_OFF + MT*40)
#define GW_OFF   (GIN_OFF + MT*20)
#define LOG_OFF  (GW_OFF + 3*MT*8)
#define PROJ_OFF (LOG_OFF + MT*8)
#define SMEMF    (PROJ_OFF + 3*128)          // 110.0 KB

// =================================================================
// FROZEN NUMERICS (passing recipe, rel_err 2.43e-4):
// layer sine = float-float glibc-poly; PE sine + gate exp = FP64;
// IEEE div; sequential-k fused-FMA GEMMs; unfused combine.
// This round: W register-prefetch + float4 A loads (bit-identical).
// =================================================================

// ---------- FP64 reference path (PE + gate exp only) ----------
struct gsincos_t {
    double sign[4];
    double c0, c1, c2, c3, c4;
    double s1, s2, s3;
};

__constant__ gsincos_t G_SINCOS[2] = {
  {
    { 1.0, -1.0, -1.0, 1.0 },
     0x1p+0,
    -0x1.ffffffd0c621cp-2,
     0x1.55553e1068f19p-5,
    -0x1.6c087e89a359dp-10,
     0x1.99343027bf8c3p-16,
    -0x1.555545995a603p-3,
     0x1.1107605230bc4p-7,
    -0x1.994eb3774cf24p-13
  },
  {
    { 1.0, -1.0, -1.0, 1.0 },
    -0x1p+0,
     0x1.ffffffd0c621cp-2,
    -0x1.55553e1068f19p-5,
     0x1.6c087e89a359dp-10,
    -0x1.99343027bf8c3p-16,
    -0x1.555545995a603p-3,
     0x1.1107605230bc4p-7,
    -0x1.994eb3774cf24p-13
  }
};

__device__ __forceinline__ uint32_t abstop12f(float x) {
    return (__float_as_uint(x) >> 20) & 0x7ffu;
}

__device__ __forceinline__ float g_sinf_poly(double x, double x2,
                                             const gsincos_t* p, int n) {
    if ((n & 1) == 0) {
        double x3 = x2 * x;
        double s1 = fma(x2, p->s3, p->s2);
        double x5 = x3 * x2;
        double s  = fma(x3, p->s1, x);
        return (float)fma(x5, s1, s);
    } else {
        double x4 = x2 * x2;
        double c2 = fma(x2, p->c4, p->c3);
        double c1 = fma(x2, p->c1, p->c0);
        double x6 = x4 * x2;
        double c  = fma(x4, p->c2, c1);
        return (float)fma(x6, c2, c);
    }
}

__device__ __forceinline__ double cw_reduce(double x, int* np) {
    double fn = rint(x * 0x1.45F306DC9C883p-1);
    double r  = fma(fn, -0x1.921FB54442D18p+0, x);
    r = fma(fn, -0x1.1A62633145C07p-54, r);
    *np = (int)fn;
    return r;
}

__device__ __forceinline__ float g_sinf(float y) {
    double x = (double)y;
    const gsincos_t* p = &G_SINCOS[0];
    uint32_t at = abstop12f(y);
    if (at < 0x3F4u) {
        if (at < 0x398u) return y;
        return g_sinf_poly(x, x * x, p, 0);
    }
    int n;
    x = cw_reduce(x, &n);
    double s = p->sign[n & 3];
    if (n & 2) p = &G_SINCOS[1];
    return g_sinf_poly(x * s, x * x, p, n);
}

__device__ __forceinline__ float g_cosf(float y) {
    double x = (double)y;
    const gsincos_t* p = &G_SINCOS[0];
    uint32_t at = abstop12f(y);
    if (at < 0x3F4u) {
        if (at < 0x398u) return 1.0f;
        return g_sinf_poly(x, x * x, p, 1);
    }
    int n;
    x = cw_reduce(x, &n);
    double s = p->sign[(n + 1) & 3];
    if ((n + 1) & 2) p = &G_SINCOS[1];
    return g_sinf_poly(x * s, x * x, p, n ^ 1);
}

__device__ __forceinline__ float g_expf(float xf) {
    double x = (double)xf;
    double fn = rint(x * 1.44269504088896338700e+00);
    double r  = fma(fn, -6.93147180369123816490e-01, x);
    r = fma(fn, -1.90821492927058770002e-10, r);
    double p =               1.0/479001600.0;
    p = fma(p, r, 1.0/39916800.0);
    p = fma(p, r, 1.0/3628800.0);
    p = fma(p, r, 1.0/362880.0);
    p = fma(p, r, 1.0/40320.0);
    p = fma(p, r, 1.0/5040.0);
    p = fma(p, r, 1.0/720.0);
    p = fma(p, r, 1.0/120.0);
    p = fma(p, r, 1.0/24.0);
    p = fma(p, r, 1.0/6.0);
    p = fma(p, r, 0.5);
    p = fma(p, r, 1.0);
    p = fma(p, r, 1.0);
    int n = (int)fn;
    double sc = __longlong_as_double((long long)(1023 + n) << 52);
    return (float)(p * sc);
}

// ---------- float-float (df) machinery ----------
struct df { float h, l; };

__device__ __forceinline__ df df_two_prod(float a, float b) {
    float p = a * b; float e = fmaf(a, b, -p); return {p, e};
}
__device__ __forceinline__ df df_fast2sum(float a, float b) {
    float s = a + b; float e = b - (s - a); return {s, e};
}
__device__ __forceinline__ df df_two_sum(float a, float b) {
    float s = a + b; float bb = s - a;
    float e = (a - (s - bb)) + (b - bb); return {s, e};
}
__device__ __forceinline__ df df_mul(df a, df b) {
    float p = a.h * b.h;
    float e = fmaf(a.h, b.h, -p);
    e = fmaf(a.h, b.l, e);
    e = fmaf(a.l, b.h, e);
    return df_fast2sum(p, e);
}
__device__ __forceinline__ df df_sqr(df a) {
    float p = a.h * a.h;
    float e = fmaf(a.h, a.h, -p);
    e = fmaf(a.h + a.h, a.l, e);
    return df_fast2sum(p, e);
}
__device__ __forceinline__ df df_add(df a, df b) {
    df s = df_two_sum(a.h, b.h);
    float e = (s.l + a.l) + b.l;
    return df_fast2sum(s.h, e);
}

#define DFC(name, dval) \
    constexpr float name##_H = (float)(dval); \
    constexpr float name##_L = (float)((dval) - (double)((float)(dval)));

DFC(INV2PI, 0x1.45F306DC9C883p-1)
constexpr double D_PI2  = 0x1.921FB54442D18p+0;
constexpr double D_PI2L = 0x1.1A62633145C07p-54;
constexpr float P2H = (float)D_PI2;
constexpr float P2M = (float)(D_PI2 - (double)P2H + D_PI2L);
constexpr float P2L = (float)(D_PI2 - (double)P2H - (double)P2M + D_PI2L);

DFC(KS1, -0x1.555545995a603p-3)
DFC(KS2,  0x1.1107605230bc4p-7)
DFC(KS3, -0x1.994eb3774cf24p-13)
DFC(KC1, -0x1.ffffffd0c621cp-2)
DFC(KC2,  0x1.55553e1068f19p-5)
DFC(KC3, -0x1.6c087e89a359dp-10)
DFC(KC4,  0x1.99343027bf8c3p-16)

__device__ __forceinline__ float ff_poly(df x, df x2, int n, bool cneg) {
    if ((n & 1) == 0) {
        df x3 = df_mul(x2, x);
        df s1 = df_add(df_mul(x2, {KS3_H, KS3_L}), {KS2_H, KS2_L});
        df x5 = df_mul(x3, x2);
        df s  = df_add(df_mul(x3, {KS1_H, KS1_L}), x);
        df r  = df_add(df_mul(x5, s1), s);
        return r.h + r.l;
    } else {
        df x4 = df_sqr(x2);
        df c2 = df_add(df_mul(x2, {KC4_H, KC4_L}), {KC3_H, KC3_L});
        df c1 = df_add(df_mul(x2, {KC1_H, KC1_L}), {1.0f, 0.0f});
        df x6 = df_mul(x4, x2);
        df c  = df_add(df_mul(x4, {KC2_H, KC2_L}), c1);
        df r  = df_add(df_mul(x6, c2), c);
        float v = r.h + r.l;
        return cneg ? -v : v;
    }
}

__device__ __forceinline__ float ff_sinf(float y) {
    uint32_t at = abstop12f(y);
    if (at < 0x3F4u) {
        if (at < 0x398u) return y;
        df x = {y, 0.0f};
        return ff_poly(x, df_sqr(x), 0, false);
    }
    df z = df_two_prod(y, INV2PI_H);
    float zl = fmaf(y, INV2PI_L, z.l);
    float fn0 = rintf(z.h);
    float d = (z.h - fn0) + zl;
    float fn = fn0 + rintf(d);
    int n = (int)fn;
    float ah = fn * P2H; float ae = fmaf(fn, P2H, -ah);
    float bh = fn * P2M; float be = fmaf(fn, P2M, -bh);
    df s1 = df_two_sum(y,   -ah);
    df s2 = df_two_sum(s1.h, -ae);
    df s3 = df_two_sum(s2.h, -bh);
    float lo = (s1.l + s2.l) + s3.l;
    lo -= be;
    lo = fmaf(fn, -P2L, lo);
    df r = df_fast2sum(s3.h, lo);
    float sg = (((n >> 1) ^ n) & 1) ? -1.0f : 1.0f;
    df xs = { r.h * sg, r.l * sg };
    return ff_poly(xs, df_sqr(xs), n, (n & 2) != 0);
}

__device__ __forceinline__ float siren_sin(float v) {
    return ff_sinf(30.0f * v);
}

// ---------------------------------------------------------------
// One dense layer for the 32-point tile (256 threads, 2x8 microtile).
// W chunks register-prefetched (next chunk LDG'd during compute);
// A loaded as float4 per 4 k-steps on full chunks. Per-element
// accumulation is the identical sequential-k fused-FMA chain.
// ---------------------------------------------------------------
template<bool DOSIN>
__device__ __forceinline__ void layer_gemm(float* sm, int inOff, int inStride, int K,
        const float* __restrict__ gW, const float* __restrict__ gB,
        int outOff, int outStride)
{
    const int tid = threadIdx.x;
    const int tx = tid & 15, ty = tid >> 4;
    const int n0 = tx * 8, m0 = ty * 2;

    float acc[2][8];
#pragma unroll
    for (int i = 0; i < 2; i++)
#pragma unroll
        for (int j = 0; j < 8; j++) acc[i][j] = 0.0f;

    float* sW = sm + W_OFF;
    const float* sA = sm + inOff;

    // prefetch chunk 0 into registers (16 floats/thread)
    float4 w0, w1, w2, w3;
    {
        const int t4 = min(32, K) * 32;
        const float4* src = (const float4*)gW;
        if (tid       < t4) w0 = src[tid];
        if (tid + 256 < t4) w1 = src[tid + 256];
        if (tid + 512 < t4) w2 = src[tid + 512];
        if (tid + 768 < t4) w3 = src[tid + 768];
    }

    for (int kc = 0; kc < K; kc += 32) {
        const int kcur = min(32, K - kc);
        const int t4 = kcur * 32;
        __syncthreads();   // previous consumers done with sW
        {
            float4* dst = (float4*)sW;
            if (tid       < t4) dst[tid]       = w0;
            if (tid + 256 < t4) dst[tid + 256] = w1;
            if (tid + 512 < t4) dst[tid + 512] = w2;
            if (tid + 768 < t4) dst[tid + 768] = w3;
        }
        if (kc + 32 < K) {   // prefetch next chunk during compute
            const int n4 = min(32, K - kc - 32) * 32;
            const float4* nsrc = (const float4*)(gW + (size_t)(kc + 32) * 128);
            if (tid       < n4) w0 = nsrc[tid];
            if (tid + 256 < n4) w1 = nsrc[tid + 256];
            if (tid + 512 < n4) w2 = nsrc[tid + 512];
            if (tid + 768 < n4) w3 = nsrc[tid + 768];
        }
        __syncthreads();

        if (kcur == 32) {
#pragma unroll
            for (int kb = 0; kb < 32; kb += 4) {
                const float4 a0 = *(const float4*)(sA + (m0 + 0) * inStride + kc + kb);
                const float4 a1 = *(const float4*)(sA + (m0 + 1) * inStride + kc + kb);
                const float* wr0 = sW + (kb + 0) * 128 + n0;
                const float* wr1 = sW + (kb + 1) * 128 + n0;
                const float* wr2 = sW + (kb + 2) * 128 + n0;
                const float* wr3 = sW + (kb + 3) * 128 + n0;
#pragma unroll
                for (int j = 0; j < 8; j++) {
                    acc[0][j] = fmaf(a0.x, wr0[j], acc[0][j]);
                    acc[1][j] = fmaf(a1.x, wr0[j], acc[1][j]);
                }
#pragma unroll
                for (int j = 0; j < 8; j++) {
                    acc[0][j] = fmaf(a0.y, wr1[j], acc[0][j]);
                    acc[1][j] = fmaf(a1.y, wr1[j], acc[1][j]);
                }
#pragma unroll
                for (int j = 0; j < 8; j++) {
                    acc[0][j] = fmaf(a0.z, wr2[j], acc[0][j]);
                    acc[1][j] = fmaf(a1.z, wr2[j], acc[1][j]);
                }
#pragma unroll
                for (int j = 0; j < 8; j++) {
                    acc[0][j] = fmaf(a0.w, wr3[j], acc[0][j]);
                    acc[1][j] = fmaf(a1.w, wr3[j], acc[1][j]);
                }
            }
        } else {
            // scalar tail path (partial chunks: K=39 tail, K=19)
            for (int k = 0; k < kcur; k++) {
                const float a0 = sA[(m0 + 0) * inStride + kc + k];
                const float a1 = sA[(m0 + 1) * inStride + kc + k];
                const float* wr = sW + k * 128 + n0;
#pragma unroll
                for (int j = 0; j < 8; j++) {
                    const float w = wr[j];
                    acc[0][j] = fmaf(a0, w, acc[0][j]);
                    acc[1][j] = fmaf(a1, w, acc[1][j]);
                }
            }
        }
    }

    float* sO = sm + outOff;
#pragma unroll
    for (int i = 0; i < 2; i++) {
#pragma unroll
        for (int j = 0; j < 8; j++) {
            float v = acc[i][j] + gB[n0 + j];
            if (DOSIN) v = siren_sin(v);
            sO[(m0 + i) * outStride + n0 + j] = v;
        }
    }
    __syncthreads();
}

// ---------------------------------------------------------------
__global__ void __launch_bounds__(NTHR, 2)
moe_fused_kernel(const float* __restrict__ coords,
                 const float* __restrict__ view_emb,
                 const float* __restrict__ proj_W,
                 const float* __restrict__ gate_W0, const float* __restrict__ gate_b0,
                 const float* __restrict__ gate_Wh, const float* __restrict__ gate_bh,
                 const float* __restrict__ gate_Wo, const float* __restrict__ gate_bo,
                 const float* __restrict__ exp_W0, const float* __restrict__ exp_b0,
                 const float* __restrict__ exp_Wh, const float* __restrict__ exp_bh,
                 const float* __restrict__ exp_Wo, const float* __restrict__ exp_bo,
                 const float* __restrict__ dec_W0, const float* __restrict__ dec_b0,
                 const float* __restrict__ dec_Wh, const float* __restrict__ dec_bh,
                 const float* __restrict__ dec_Wo, const float* __restrict__ dec_bo,
                 float* __restrict__ out, int npts)
{
    extern __shared__ float sm[];
    const int tid = threadIdx.x;
    const int gm0 = blockIdx.x * MT;

    // ---------- positional encoding: FP64 path (chain head) ----------
    for (int idx = tid; idx < MT * PED; idx += NTHR) {
        int m = idx / PED, c = idx % PED;
        float v;
        if (c < 3) {
            v = coords[(size_t)(gm0 + m) * 3 + c];
        } else {
            int r = c - 3;
            int i = r / 12;
            int rr = r % 12;
            int f = rr % 6;
            float x = coords[(size_t)(gm0 + m) * 3 + i];
            float freq = 3.14159265358979323846f * (float)(1 << f);
            float a = x * freq;
            v = (rr < 6) ? g_sinf(a) : g_cosf(a);
        }
        sm[PE_OFF + m * 40 + c] = v;
    }

    // ---------- projvec[v][n] = vemb[v] @ proj_W ----------
    for (int idx = tid; idx < NV * 128; idx += NTHR) {
        int v = idx >> 7, n = idx & 127;
        float a = 0.0f;
#pragma unroll
        for (int k = 0; k < VED; k++)
            a = fmaf(view_emb[v * VED + k], proj_W[k * 128 + n], a);
        sm[PROJ_OFF + idx] = a;
    }

    for (int idx = tid; idx < NV * MT * 128; idx += NTHR)
        sm[HACC_OFF + idx] = 0.0f;
    __syncthreads();

    // ---------- gate MLP per view -> top-2 normalized weights ----------
    for (int v = 0; v < NV; v++) {
        __syncthreads();
        for (int idx = tid; idx < MT * 20; idx += NTHR) {
            int m = idx / 20, c = idx % 20;
            float x;
            if (c < 3)       x = coords[(size_t)(gm0 + m) * 3 + c];
            else if (c < 19) x = view_emb[v * VED + (c - 3)];
            else             x = 0.0f;
            sm[GIN_OFF + idx] = x;
        }
        layer_gemm<true>(sm, GIN_OFF, 20, GIND, gate_W0, gate_b0, SA_OFF, SSTR);
        layer_gemm<true>(sm, SA_OFF, SSTR, HID, gate_Wh,             gate_bh,       SB_OFF, SSTR);
        layer_gemm<true>(sm, SB_OFF, SSTR, HID, gate_Wh + HID * HID, gate_bh + HID, SA_OFF, SSTR);

        for (int idx = tid; idx < MT * NE; idx += NTHR) {
            int m = idx / NE, e = idx % NE;
            float a = 0.0f;
            const float* h = sm + SA_OFF + m * SSTR;
            for (int k = 0; k < HID; k++)
                a = fmaf(h[k], gate_Wo[k * NE + e], a);
            sm[LOG_OFF + m * 8 + e] = a + gate_bo[e];
        }
        __syncthreads();

        // softmax + top-2 + renormalize: FP64 exp, IEEE div, ref tie order
        if (tid < MT) {
            float l[NE];
            float mx = -1e30f;
            for (int e = 0; e < NE; e++) { l[e] = sm[LOG_OFF + tid * 8 + e]; mx = fmaxf(mx, l[e]); }
            float p[NE]; float s = 0.0f;
            for (int e = 0; e < NE; e++) { p[e] = g_expf(l[e] - mx); s += p[e]; }
            float p1 = -1.0f, p2 = -1.0f; int i1 = -1, i2 = -1;
            for (int e = 0; e < NE; e++) {
                float pe_ = __fdiv_rn(p[e], s);
                p[e] = pe_;
                if (pe_ > p1)      { p2 = p1; i2 = i1; p1 = pe_; i1 = e; }
                else if (pe_ > p2) { p2 = pe_; i2 = e; }
            }
            float den = (p1 + p2) + 1e-9f;
            for (int e = 0; e < NE; e++) {
                float w = 0.0f;
                if (e == i1)      w = __fdiv_rn(p1, den);
                else if (e == i2) w = __fdiv_rn(p2, den);
                sm[GW_OFF + (v * MT + tid) * 8 + e] = w;
            }
        }
        __syncthreads();
    }

    // ---------- experts ----------
    for (int e = 0; e < NE; e++) {
        const float* W0 = exp_W0 + (size_t)e * PED * HID;
        const float* Wh = exp_Wh + (size_t)e * 2 * HID * HID;
        const float* Wo = exp_Wo + (size_t)e * HID * FDIM;
        layer_gemm<true >(sm, PE_OFF, 40, PED, W0,             exp_b0 + e * HID,           SA_OFF, SSTR);
        layer_gemm<true >(sm, SA_OFF, SSTR, HID, Wh,             exp_bh + e * 2 * HID,       SB_OFF, SSTR);
        layer_gemm<true >(sm, SB_OFF, SSTR, HID, Wh + HID * HID, exp_bh + e * 2 * HID + HID, SA_OFF, SSTR);
        layer_gemm<false>(sm, SA_OFF, SSTR, HID, Wo,             exp_bo + e * FDIM,          SB_OFF, SSTR);

        const int tx = tid & 15, ty = tid >> 4;
        const int n0 = tx * 8, m0 = ty * 2;
#pragma unroll
        for (int v = 0; v < NV; v++) {
#pragma unroll
            for (int i = 0; i < 2; i++) {
                const float wv = sm[GW_OFF + (v * MT + m0 + i) * 8 + e];
                float* hb = sm + HACC_OFF + ((v * MT + m0 + i) << 7) + n0;
                const float* fb = sm + SB_OFF + (m0 + i) * SSTR + n0;
#pragma unroll
                for (int j = 0; j < 8; j++) {
                    float t = __fmul_rn(wv, fb[j]);
                    hb[j] = __fadd_rn(hb[j], t);
                }
            }
        }
        __syncthreads();
    }

    // add proj AFTER the expert sum
    for (int idx = tid; idx < NV * MT * 128; idx += NTHR) {
        int v = idx / (MT * 128);
        int n = idx & 127;
        sm[HACC_OFF + idx] = __fadd_rn(sm[HACC_OFF + idx], sm[PROJ_OFF + v * 128 + n]);
    }
    __syncthreads();

    // ---------- per-view decoder ----------
    for (int v = 0; v < NV; v++) {
        const float* W0 = dec_W0 + (size_t)v * FDIM * HID;
        const float* Wh = dec_Wh + (size_t)v * 2 * HID * HID;
        layer_gemm<true>(sm, HACC_OFF + v * MT * 128, 128, FDIM, W0, dec_b0 + v * HID, SA_OFF, SSTR);
        layer_gemm<true>(sm, SA_OFF, SSTR, HID, Wh,             dec_bh + v * 2 * HID,       SB_OFF, SSTR);
        layer_gemm<true>(sm, SB_OFF, SSTR, HID, Wh + HID * HID, dec_bh + v * 2 * HID + HID, SA_OFF, SSTR);

        for (int idx = tid; idx < MT * OUTD; idx += NTHR) {
            int m = idx / OUTD, o = idx % OUTD;
            float a = 0.0f;
            const float* h = sm + SA_OFF + m * SSTR;
            const float* w = dec_Wo + (size_t)v * HID * OUTD;
            for (int k = 0; k < HID; k++)
                a = fmaf(h[k], w[k * OUTD + o], a);
            out[((size_t)v * npts + gm0 + m) * OUTD + o] = a + dec_bo[v * OUTD + o];
        }
        __syncthreads();
    }
}

extern "C" void kernel_launch(void* const* d_in, const int* in_sizes, int n_in,
                              void* d_out, int out_size) {
    const float* coords   = (const float*)d_in[0];
    const float* view_emb = (const float*)d_in[1];
    const float* proj_W   = (const float*)d_in[2];
    const float* gate_W0  = (const float*)d_in[3];
    const float* gate_b0  = (const float*)d_in[4];
    const float* gate_Wh  = (const float*)d_in[5];
    const float* gate_bh  = (const float*)d_in[6];
    const float* gate_Wo  = (const float*)d_in[7];
    const float* gate_bo  = (const float*)d_in[8];
    const float* exp_W0   = (const float*)d_in[9];
    const float* exp_b0   = (const float*)d_in[10];
    const float* exp_Wh   = (const float*)d_in[11];
    const float* exp_bh   = (const float*)d_in[12];
    const float* exp_Wo   = (const float*)d_in[13];
    const float* exp_bo   = (const float*)d_in[14];
    const float* dec_W0   = (const float*)d_in[15];
    const float* dec_b0   = (const float*)d_in[16];
    const float* dec_Wh   = (const float*)d_in[17];
    const float* dec_bh   = (const float*)d_in[18];
    const float* dec_Wo   = (const float*)d_in[19];
    const float* dec_bo   = (const float*)d_in[20];

    const int npts = in_sizes[0] / 3;      // 65536
    const int grid = npts / MT;            // 2048
    const size_t shmem = (size_t)SMEMF * sizeof(float);   // 110.0 KB

    cudaFuncSetAttribute(moe_fused_kernel,
                         cudaFuncAttributeMaxDynamicSharedMemorySize, (int)shmem);

    moe_fused_kernel<<<grid, NTHR, shmem>>>(
        coords, view_emb, proj_W,
        gate_W0, gate_b0, gate_Wh, gate_bh, gate_Wo, gate_bo,
        exp_W0, exp_b0, exp_Wh, exp_bh, exp_Wo, exp_bo,
        dec_W0, dec_b0, dec_Wh, dec_bh, dec_Wo, dec_bo,
        (float*)d_out, npts);
}

// round 17
// speedup vs baseline: 1.3176x; 1.0292x over previous
#include <cuda_runtime.h>
#include <math.h>
#include <stdint.h>

// ---------------- problem constants ----------------
#define NE    7
#define NV    3
#define FDIM  128
#define HID   128
#define VED   16
#define PED   39
#define GIND  19
#define OUTD  3

// ---------------- tiling (best known: R14/R16 shape) ----------------
#define MT    32     // points per block (2 blocks/SM)
#define NTHR  256    // 8 warps; microtile 2(m) x 8(n), grid 16 x 16

// ---------------- shared memory layout (floats) ----------------
#define SSTR     132
#define SA_OFF   0
#define SB_OFF   (MT*SSTR)
#define HACC_OFF (SB_OFF + MT*SSTR)
#define W_OFF    (HACC_OFF + 3*MT*128)
#define PE_OFF   (W_OFF + 32*128)
#define GIN_OFF  (PE_OFF + MT*40)
#define GW_OFF   (GIN_OFF + MT*20)
#define LOG_OFF  (GW_OFF + 3*MT*8)
#define PROJ_OFF (LOG_OFF + MT*8)
#define SMEMF    (PROJ_OFF + 3*128)          // 110.0 KB

// =================================================================
// FROZEN NUMERICS (passing recipe, rel_err 2.43e-4):
// layer sine = float-float glibc-poly; PE sine + gate exp = FP64;
// IEEE div; sequential-k fused-FMA GEMMs; unfused combine.
// This round: GEMM inner loop packed into fma.rn.f32x2 — each
// 64-bit lane is the identical IEEE f32 FMA in identical k-order
// (bit-identical output, half the FMA-pipe instructions).
// =================================================================

// ---------- FP64 reference path (PE + gate exp only) ----------
struct gsincos_t {
    double sign[4];
    double c0, c1, c2, c3, c4;
    double s1, s2, s3;
};

__constant__ gsincos_t G_SINCOS[2] = {
  {
    { 1.0, -1.0, -1.0, 1.0 },
     0x1p+0,
    -0x1.ffffffd0c621cp-2,
     0x1.55553e1068f19p-5,
    -0x1.6c087e89a359dp-10,
     0x1.99343027bf8c3p-16,
    -0x1.555545995a603p-3,
     0x1.1107605230bc4p-7,
    -0x1.994eb3774cf24p-13
  },
  {
    { 1.0, -1.0, -1.0, 1.0 },
    -0x1p+0,
     0x1.ffffffd0c621cp-2,
    -0x1.55553e1068f19p-5,
     0x1.6c087e89a359dp-10,
    -0x1.99343027bf8c3p-16,
    -0x1.555545995a603p-3,
     0x1.1107605230bc4p-7,
    -0x1.994eb3774cf24p-13
  }
};

__device__ __forceinline__ uint32_t abstop12f(float x) {
    return (__float_as_uint(x) >> 20) & 0x7ffu;
}

__device__ __forceinline__ float g_sinf_poly(double x, double x2,
                                             const gsincos_t* p, int n) {
    if ((n & 1) == 0) {
        double x3 = x2 * x;
        double s1 = fma(x2, p->s3, p->s2);
        double x5 = x3 * x2;
        double s  = fma(x3, p->s1, x);
        return (float)fma(x5, s1, s);
    } else {
        double x4 = x2 * x2;
        double c2 = fma(x2, p->c4, p->c3);
        double c1 = fma(x2, p->c1, p->c0);
        double x6 = x4 * x2;
        double c  = fma(x4, p->c2, c1);
        return (float)fma(x6, c2, c);
    }
}

__device__ __forceinline__ double cw_reduce(double x, int* np) {
    double fn = rint(x * 0x1.45F306DC9C883p-1);
    double r  = fma(fn, -0x1.921FB54442D18p+0, x);
    r = fma(fn, -0x1.1A62633145C07p-54, r);
    *np = (int)fn;
    return r;
}

__device__ __forceinline__ float g_sinf(float y) {
    double x = (double)y;
    const gsincos_t* p = &G_SINCOS[0];
    uint32_t at = abstop12f(y);
    if (at < 0x3F4u) {
        if (at < 0x398u) return y;
        return g_sinf_poly(x, x * x, p, 0);
    }
    int n;
    x = cw_reduce(x, &n);
    double s = p->sign[n & 3];
    if (n & 2) p = &G_SINCOS[1];
    return g_sinf_poly(x * s, x * x, p, n);
}

__device__ __forceinline__ float g_cosf(float y) {
    double x = (double)y;
    const gsincos_t* p = &G_SINCOS[0];
    uint32_t at = abstop12f(y);
    if (at < 0x3F4u) {
        if (at < 0x398u) return 1.0f;
        return g_sinf_poly(x, x * x, p, 1);
    }
    int n;
    x = cw_reduce(x, &n);
    double s = p->sign[(n + 1) & 3];
    if ((n + 1) & 2) p = &G_SINCOS[1];
    return g_sinf_poly(x * s, x * x, p, n ^ 1);
}

__device__ __forceinline__ float g_expf(float xf) {
    double x = (double)xf;
    double fn = rint(x * 1.44269504088896338700e+00);
    double r  = fma(fn, -6.93147180369123816490e-01, x);
    r = fma(fn, -1.90821492927058770002e-10, r);
    double p =               1.0/479001600.0;
    p = fma(p, r, 1.0/39916800.0);
    p = fma(p, r, 1.0/3628800.0);
    p = fma(p, r, 1.0/362880.0);
    p = fma(p, r, 1.0/40320.0);
    p = fma(p, r, 1.0/5040.0);
    p = fma(p, r, 1.0/720.0);
    p = fma(p, r, 1.0/120.0);
    p = fma(p, r, 1.0/24.0);
    p = fma(p, r, 1.0/6.0);
    p = fma(p, r, 0.5);
    p = fma(p, r, 1.0);
    p = fma(p, r, 1.0);
    int n = (int)fn;
    double sc = __longlong_as_double((long long)(1023 + n) << 52);
    return (float)(p * sc);
}

// ---------- float-float (df) machinery ----------
struct df { float h, l; };

__device__ __forceinline__ df df_two_prod(float a, float b) {
    float p = a * b; float e = fmaf(a, b, -p); return {p, e};
}
__device__ __forceinline__ df df_fast2sum(float a, float b) {
    float s = a + b; float e = b - (s - a); return {s, e};
}
__device__ __forceinline__ df df_two_sum(float a, float b) {
    float s = a + b; float bb = s - a;
    float e = (a - (s - bb)) + (b - bb); return {s, e};
}
__device__ __forceinline__ df df_mul(df a, df b) {
    float p = a.h * b.h;
    float e = fmaf(a.h, b.h, -p);
    e = fmaf(a.h, b.l, e);
    e = fmaf(a.l, b.h, e);
    return df_fast2sum(p, e);
}
__device__ __forceinline__ df df_sqr(df a) {
    float p = a.h * a.h;
    float e = fmaf(a.h, a.h, -p);
    e = fmaf(a.h + a.h, a.l, e);
    return df_fast2sum(p, e);
}
__device__ __forceinline__ df df_add(df a, df b) {
    df s = df_two_sum(a.h, b.h);
    float e = (s.l + a.l) + b.l;
    return df_fast2sum(s.h, e);
}

#define DFC(name, dval) \
    constexpr float name##_H = (float)(dval); \
    constexpr float name##_L = (float)((dval) - (double)((float)(dval)));

DFC(INV2PI, 0x1.45F306DC9C883p-1)
constexpr double D_PI2  = 0x1.921FB54442D18p+0;
constexpr double D_PI2L = 0x1.1A62633145C07p-54;
constexpr float P2H = (float)D_PI2;
constexpr float P2M = (float)(D_PI2 - (double)P2H + D_PI2L);
constexpr float P2L = (float)(D_PI2 - (double)P2H - (double)P2M + D_PI2L);

DFC(KS1, -0x1.555545995a603p-3)
DFC(KS2,  0x1.1107605230bc4p-7)
DFC(KS3, -0x1.994eb3774cf24p-13)
DFC(KC1, -0x1.ffffffd0c621cp-2)
DFC(KC2,  0x1.55553e1068f19p-5)
DFC(KC3, -0x1.6c087e89a359dp-10)
DFC(KC4,  0x1.99343027bf8c3p-16)

__device__ __forceinline__ float ff_poly(df x, df x2, int n, bool cneg) {
    if ((n & 1) == 0) {
        df x3 = df_mul(x2, x);
        df s1 = df_add(df_mul(x2, {KS3_H, KS3_L}), {KS2_H, KS2_L});
        df x5 = df_mul(x3, x2);
        df s  = df_add(df_mul(x3, {KS1_H, KS1_L}), x);
        df r  = df_add(df_mul(x5, s1), s);
        return r.h + r.l;
    } else {
        df x4 = df_sqr(x2);
        df c2 = df_add(df_mul(x2, {KC4_H, KC4_L}), {KC3_H, KC3_L});
        df c1 = df_add(df_mul(x2, {KC1_H, KC1_L}), {1.0f, 0.0f});
        df x6 = df_mul(x4, x2);
        df c  = df_add(df_mul(x4, {KC2_H, KC2_L}), c1);
        df r  = df_add(df_mul(x6, c2), c);
        float v = r.h + r.l;
        return cneg ? -v : v;
    }
}

__device__ __forceinline__ float ff_sinf(float y) {
    uint32_t at = abstop12f(y);
    if (at < 0x3F4u) {
        if (at < 0x398u) return y;
        df x = {y, 0.0f};
        return ff_poly(x, df_sqr(x), 0, false);
    }
    df z = df_two_prod(y, INV2PI_H);
    float zl = fmaf(y, INV2PI_L, z.l);
    float fn0 = rintf(z.h);
    float d = (z.h - fn0) + zl;
    float fn = fn0 + rintf(d);
    int n = (int)fn;
    float ah = fn * P2H; float ae = fmaf(fn, P2H, -ah);
    float bh = fn * P2M; float be = fmaf(fn, P2M, -bh);
    df s1 = df_two_sum(y,   -ah);
    df s2 = df_two_sum(s1.h, -ae);
    df s3 = df_two_sum(s2.h, -bh);
    float lo = (s1.l + s2.l) + s3.l;
    lo -= be;
    lo = fmaf(fn, -P2L, lo);
    df r = df_fast2sum(s3.h, lo);
    float sg = (((n >> 1) ^ n) & 1) ? -1.0f : 1.0f;
    df xs = { r.h * sg, r.l * sg };
    return ff_poly(xs, df_sqr(xs), n, (n & 2) != 0);
}

__device__ __forceinline__ float siren_sin(float v) {
    return ff_sinf(30.0f * v);
}

// ---------- packed f32x2 helpers (Blackwell native) ----------
__device__ __forceinline__ unsigned long long pack2(float x, float y) {
    unsigned long long r;
    asm("mov.b64 %0, {%1, %2};" : "=l"(r) : "f"(x), "f"(y));
    return r;
}
__device__ __forceinline__ void unpack2(unsigned long long v, float& x, float& y) {
    asm("mov.b64 {%0, %1}, %2;" : "=f"(x), "=f"(y) : "l"(v));
}
__device__ __forceinline__ unsigned long long fma2(unsigned long long a,
                                                   unsigned long long b,
                                                   unsigned long long c) {
    unsigned long long d;
    asm("fma.rn.f32x2 %0, %1, %2, %3;" : "=l"(d) : "l"(a), "l"(b), "l"(c));
    return d;
}

// ---------------------------------------------------------------
// One dense layer for the 32-point tile (256 threads, 2x8 microtile).
// W register-prefetched; full chunks computed with fma.rn.f32x2
// (n-pairs packed in 64-bit lanes; per-lane IEEE FMA in identical
// k-order -> bit-identical to the scalar version). Scalar tail path
// for partial chunks.
// ---------------------------------------------------------------
template<bool DOSIN>
__device__ __forceinline__ void layer_gemm(float* sm, int inOff, int inStride, int K,
        const float* __restrict__ gW, const float* __restrict__ gB,
        int outOff, int outStride)
{
    const int tid = threadIdx.x;
    const int tx = tid & 15, ty = tid >> 4;
    const int n0 = tx * 8, m0 = ty * 2;

    // packed accumulators: acc2[i][j'] = {acc[i][2j'], acc[i][2j'+1]}
    unsigned long long acc2[2][4];
#pragma unroll
    for (int i = 0; i < 2; i++)
#pragma unroll
        for (int j = 0; j < 4; j++) acc2[i][j] = 0ULL;   // {0.0f, 0.0f}

    float* sW = sm + W_OFF;
    const float* sA = sm + inOff;

    // prefetch chunk 0 into registers (16 floats/thread)
    float4 w0, w1, w2, w3;
    {
        const int t4 = min(32, K) * 32;
        const float4* src = (const float4*)gW;
        if (tid       < t4) w0 = src[tid];
        if (tid + 256 < t4) w1 = src[tid + 256];
        if (tid + 512 < t4) w2 = src[tid + 512];
        if (tid + 768 < t4) w3 = src[tid + 768];
    }

    for (int kc = 0; kc < K; kc += 32) {
        const int kcur = min(32, K - kc);
        const int t4 = kcur * 32;
        __syncthreads();
        {
            float4* dst = (float4*)sW;
            if (tid       < t4) dst[tid]       = w0;
            if (tid + 256 < t4) dst[tid + 256] = w1;
            if (tid + 512 < t4) dst[tid + 512] = w2;
            if (tid + 768 < t4) dst[tid + 768] = w3;
        }
        if (kc + 32 < K) {
            const int n4 = min(32, K - kc - 32) * 32;
            const float4* nsrc = (const float4*)(gW + (size_t)(kc + 32) * 128);
            if (tid       < n4) w0 = nsrc[tid];
            if (tid + 256 < n4) w1 = nsrc[tid + 256];
            if (tid + 512 < n4) w2 = nsrc[tid + 512];
            if (tid + 768 < n4) w3 = nsrc[tid + 768];
        }
        __syncthreads();

        if (kcur == 32) {
#pragma unroll
            for (int kb = 0; kb < 32; kb += 4) {
                const float4 a0 = *(const float4*)(sA + (m0 + 0) * inStride + kc + kb);
                const float4 a1 = *(const float4*)(sA + (m0 + 1) * inStride + kc + kb);
#pragma unroll
                for (int ks = 0; ks < 4; ks++) {
                    const float av0 = (ks == 0) ? a0.x : (ks == 1) ? a0.y : (ks == 2) ? a0.z : a0.w;
                    const float av1 = (ks == 0) ? a1.x : (ks == 1) ? a1.y : (ks == 2) ? a1.z : a1.w;
                    const unsigned long long ap0 = pack2(av0, av0);
                    const unsigned long long ap1 = pack2(av1, av1);
                    // 8 W floats = 2x LDS.128 = 4 packed 64-bit lanes
                    const ulonglong2 wA = *(const ulonglong2*)(sW + (kb + ks) * 128 + n0);
                    const ulonglong2 wB = *(const ulonglong2*)(sW + (kb + ks) * 128 + n0 + 4);
                    acc2[0][0] = fma2(ap0, wA.x, acc2[0][0]);
                    acc2[1][0] = fma2(ap1, wA.x, acc2[1][0]);
                    acc2[0][1] = fma2(ap0, wA.y, acc2[0][1]);
                    acc2[1][1] = fma2(ap1, wA.y, acc2[1][1]);
                    acc2[0][2] = fma2(ap0, wB.x, acc2[0][2]);
                    acc2[1][2] = fma2(ap1, wB.x, acc2[1][2]);
                    acc2[0][3] = fma2(ap0, wB.y, acc2[0][3]);
                    acc2[1][3] = fma2(ap1, wB.y, acc2[1][3]);
                }
            }
        } else {
            // scalar tail path (partial chunks: K=39 tail, K=19)
            // identical per-lane ops: unpack, scalar fmaf, repack
            for (int k = 0; k < kcur; k++) {
                const float a0 = sA[(m0 + 0) * inStride + kc + k];
                const float a1 = sA[(m0 + 1) * inStride + kc + k];
                const float* wr = sW + k * 128 + n0;
#pragma unroll
                for (int i = 0; i < 2; i++) {
                    const float ai = (i == 0) ? a0 : a1;
#pragma unroll
                    for (int j = 0; j < 4; j++) {
                        float lo, hi;
                        unpack2(acc2[i][j], lo, hi);
                        lo = fmaf(ai, wr[2 * j],     lo);
                        hi = fmaf(ai, wr[2 * j + 1], hi);
                        acc2[i][j] = pack2(lo, hi);
                    }
                }
            }
        }
    }

    float* sO = sm + outOff;
#pragma unroll
    for (int i = 0; i < 2; i++) {
#pragma unroll
        for (int j = 0; j < 4; j++) {
            float lo, hi;
            unpack2(acc2[i][j], lo, hi);
            float v0 = lo + gB[n0 + 2 * j];
            float v1 = hi + gB[n0 + 2 * j + 1];
            if (DOSIN) { v0 = siren_sin(v0); v1 = siren_sin(v1); }
            sO[(m0 + i) * outStride + n0 + 2 * j]     = v0;
            sO[(m0 + i) * outStride + n0 + 2 * j + 1] = v1;
        }
    }
    __syncthreads();
}

// ---------------------------------------------------------------
__global__ void __launch_bounds__(NTHR, 2)
moe_fused_kernel(const float* __restrict__ coords,
                 const float* __restrict__ view_emb,
                 const float* __restrict__ proj_W,
                 const float* __restrict__ gate_W0, const float* __restrict__ gate_b0,
                 const float* __restrict__ gate_Wh, const float* __restrict__ gate_bh,
                 const float* __restrict__ gate_Wo, const float* __restrict__ gate_bo,
                 const float* __restrict__ exp_W0, const float* __restrict__ exp_b0,
                 const float* __restrict__ exp_Wh, const float* __restrict__ exp_bh,
                 const float* __restrict__ exp_Wo, const float* __restrict__ exp_bo,
                 const float* __restrict__ dec_W0, const float* __restrict__ dec_b0,
                 const float* __restrict__ dec_Wh, const float* __restrict__ dec_bh,
                 const float* __restrict__ dec_Wo, const float* __restrict__ dec_bo,
                 float* __restrict__ out, int npts)
{
    extern __shared__ float sm[];
    const int tid = threadIdx.x;
    const int gm0 = blockIdx.x * MT;

    // ---------- positional encoding: FP64 path (chain head) ----------
    for (int idx = tid; idx < MT * PED; idx += NTHR) {
        int m = idx / PED, c = idx % PED;
        float v;
        if (c < 3) {
            v = coords[(size_t)(gm0 + m) * 3 + c];
        } else {
            int r = c - 3;
            int i = r / 12;
            int rr = r % 12;
            int f = rr % 6;
            float x = coords[(size_t)(gm0 + m) * 3 + i];
            float freq = 3.14159265358979323846f * (float)(1 << f);
            float a = x * freq;
            v = (rr < 6) ? g_sinf(a) : g_cosf(a);
        }
        sm[PE_OFF + m * 40 + c] = v;
    }

    // ---------- projvec[v][n] = vemb[v] @ proj_W ----------
    for (int idx = tid; idx < NV * 128; idx += NTHR) {
        int v = idx >> 7, n = idx & 127;
        float a = 0.0f;
#pragma unroll
        for (int k = 0; k < VED; k++)
            a = fmaf(view_emb[v * VED + k], proj_W[k * 128 + n], a);
        sm[PROJ_OFF + idx] = a;
    }

    for (int idx = tid; idx < NV * MT * 128; idx += NTHR)
        sm[HACC_OFF + idx] = 0.0f;
    __syncthreads();

    // ---------- gate MLP per view -> top-2 normalized weights ----------
    for (int v = 0; v < NV; v++) {
        __syncthreads();
        for (int idx = tid; idx < MT * 20; idx += NTHR) {
            int m = idx / 20, c = idx % 20;
            float x;
            if (c < 3)       x = coords[(size_t)(gm0 + m) * 3 + c];
            else if (c < 19) x = view_emb[v * VED + (c - 3)];
            else             x = 0.0f;
            sm[GIN_OFF + idx] = x;
        }
        layer_gemm<true>(sm, GIN_OFF, 20, GIND, gate_W0, gate_b0, SA_OFF, SSTR);
        layer_gemm<true>(sm, SA_OFF, SSTR, HID, gate_Wh,             gate_bh,       SB_OFF, SSTR);
        layer_gemm<true>(sm, SB_OFF, SSTR, HID, gate_Wh + HID * HID, gate_bh + HID, SA_OFF, SSTR);

        for (int idx = tid; idx < MT * NE; idx += NTHR) {
            int m = idx / NE, e = idx % NE;
            float a = 0.0f;
            const float* h = sm + SA_OFF + m * SSTR;
            for (int k = 0; k < HID; k++)
                a = fmaf(h[k], gate_Wo[k * NE + e], a);
            sm[LOG_OFF + m * 8 + e] = a + gate_bo[e];
        }
        __syncthreads();

        // softmax + top-2 + renormalize: FP64 exp, IEEE div, ref tie order
        if (tid < MT) {
            float l[NE];
            float mx = -1e30f;
            for (int e = 0; e < NE; e++) { l[e] = sm[LOG_OFF + tid * 8 + e]; mx = fmaxf(mx, l[e]); }
            float p[NE]; float s = 0.0f;
            for (int e = 0; e < NE; e++) { p[e] = g_expf(l[e] - mx); s += p[e]; }
            float p1 = -1.0f, p2 = -1.0f; int i1 = -1, i2 = -1;
            for (int e = 0; e < NE; e++) {
                float pe_ = __fdiv_rn(p[e], s);
                p[e] = pe_;
                if (pe_ > p1)      { p2 = p1; i2 = i1; p1 = pe_; i1 = e; }
                else if (pe_ > p2) { p2 = pe_; i2 = e; }
            }
            float den = (p1 + p2) + 1e-9f;
            for (int e = 0; e < NE; e++) {
                float w = 0.0f;
                if (e == i1)      w = __fdiv_rn(p1, den);
                else if (e == i2) w = __fdiv_rn(p2, den);
                sm[GW_OFF + (v * MT + tid) * 8 + e] = w;
            }
        }
        __syncthreads();
    }

    // ---------- experts ----------
    for (int e = 0; e < NE; e++) {
        const float* W0 = exp_W0 + (size_t)e * PED * HID;
        const float* Wh = exp_Wh + (size_t)e * 2 * HID * HID;
        const float* Wo = exp_Wo + (size_t)e * HID * FDIM;
        layer_gemm<true >(sm, PE_OFF, 40, PED, W0,             exp_b0 + e * HID,           SA_OFF, SSTR);
        layer_gemm<true >(sm, SA_OFF, SSTR, HID, Wh,             exp_bh + e * 2 * HID,       SB_OFF, SSTR);
        layer_gemm<true >(sm, SB_OFF, SSTR, HID, Wh + HID * HID, exp_bh + e * 2 * HID + HID, SA_OFF, SSTR);
        layer_gemm<false>(sm, SA_OFF, SSTR, HID, Wo,             exp_bo + e * FDIM,          SB_OFF, SSTR);

        const int tx = tid & 15, ty = tid >> 4;
        const int n0 = tx * 8, m0 = ty * 2;
#pragma unroll
        for (int v = 0; v < NV; v++) {
#pragma unroll
            for (int i = 0; i < 2; i++) {
                const float wv = sm[GW_OFF + (v * MT + m0 + i) * 8 + e];
                float* hb = sm + HACC_OFF + ((v * MT + m0 + i) << 7) + n0;
                const float* fb = sm + SB_OFF + (m0 + i) * SSTR + n0;
#pragma unroll
                for (int j = 0; j < 8; j++) {
                    float t = __fmul_rn(wv, fb[j]);
                    hb[j] = __fadd_rn(hb[j], t);
                }
            }
        }
        __syncthreads();
    }

    // add proj AFTER the expert sum
    for (int idx = tid; idx < NV * MT * 128; idx += NTHR) {
        int v = idx / (MT * 128);
        int n = idx & 127;
        sm[HACC_OFF + idx] = __fadd_rn(sm[HACC_OFF + idx], sm[PROJ_OFF + v * 128 + n]);
    }
    __syncthreads();

    // ---------- per-view decoder ----------
    for (int v = 0; v < NV; v++) {
        const float* W0 = dec_W0 + (size_t)v * FDIM * HID;
        const float* Wh = dec_Wh + (size_t)v * 2 * HID * HID;
        layer_gemm<true>(sm, HACC_OFF + v * MT * 128, 128, FDIM, W0, dec_b0 + v * HID, SA_OFF, SSTR);
        layer_gemm<true>(sm, SA_OFF, SSTR, HID, Wh,             dec_bh + v * 2 * HID,       SB_OFF, SSTR);
        layer_gemm<true>(sm, SB_OFF, SSTR, HID, Wh + HID * HID, dec_bh + v * 2 * HID + HID, SA_OFF, SSTR);

        for (int idx = tid; idx < MT * OUTD; idx += NTHR) {
            int m = idx / OUTD, o = idx % OUTD;
            float a = 0.0f;
            const float* h = sm + SA_OFF + m * SSTR;
            const float* w = dec_Wo + (size_t)v * HID * OUTD;
            for (int k = 0; k < HID; k++)
                a = fmaf(h[k], w[k * OUTD + o], a);
            out[((size_t)v * npts + gm0 + m) * OUTD + o] = a + dec_bo[v * OUTD + o];
        }
        __syncthreads();
    }
}

extern "C" void kernel_launch(void* const* d_in, const int* in_sizes, int n_in,
                              void* d_out, int out_size) {
    const float* coords   = (const float*)d_in[0];
    const float* view_emb = (const float*)d_in[1];
    const float* proj_W   = (const float*)d_in[2];
    const float* gate_W0  = (const float*)d_in[3];
    const float* gate_b0  = (const float*)d_in[4];
    const float* gate_Wh  = (const float*)d_in[5];
    const float* gate_bh  = (const float*)d_in[6];
    const float* gate_Wo  = (const float*)d_in[7];
    const float* gate_bo  = (const float*)d_in[8];
    const float* exp_W0   = (const float*)d_in[9];
    const float* exp_b0   = (const float*)d_in[10];
    const float* exp_Wh   = (const float*)d_in[11];
    const float* exp_bh   = (const float*)d_in[12];
    const float* exp_Wo   = (const float*)d_in[13];
    const float* exp_bo   = (const float*)d_in[14];
    const float* dec_W0   = (const float*)d_in[15];
    const float* dec_b0   = (const float*)d_in[16];
    const float* dec_Wh   = (const float*)d_in[17];
    const float* dec_bh   = (const float*)d_in[18];
    const float* dec_Wo   = (const float*)d_in[19];
    const float* dec_bo   = (const float*)d_in[20];

    const int npts = in_sizes[0] / 3;      // 65536
    const int grid = npts / MT;            // 2048
    const size_t shmem = (size_t)SMEMF * sizeof(float);   // 110.0 KB

    cudaFuncSetAttribute(moe_fused_kernel,
                         cudaFuncAttributeMaxDynamicSharedMemorySize, (int)shmem);

    moe_fused_kernel<<<grid, NTHR, shmem>>>(
        coords, view_emb, proj_W,
        gate_W0, gate_b0, gate_Wh, gate_bh, gate_Wo, gate_bo,
        exp_W0, exp_b0, exp_Wh, exp_bh, exp_Wo, exp_bo,
        dec_W0, dec_b0, dec_Wh, dec_bh, dec_Wo, dec_bo,
        (float*)d_out, npts);
}